// round 15
// baseline (speedup 1.0000x reference)
#include <cuda_runtime.h>
#include <cuda_bf16.h>
#include <cstdint>
#include <math.h>

#define BB 4
#define NN 4096
#define DD 1024
#define HH 16
#define RR 64
#define HDIM 64
#define MTOT (BB*NN)   // 16384
#define MHALF (MTOT/2) // 8192
#define LRS 8          // lowrank N-split

// ---------------------------------------------------------------------------
// Scratch (device globals — no allocation allowed)
// ---------------------------------------------------------------------------
__device__ __nv_bfloat16 g_xh[MTOT*DD];
__device__ __nv_bfloat16 g_xl[MTOT*DD];
__device__ __nv_bfloat16 g_Wh[4*DD*DD];   // 0=Wq 1=Wk 2=Wv 3=Wo
__device__ __nv_bfloat16 g_Wl[4*DD*DD];
__device__ float g_Q[MTOT*DD];
__device__ __nv_bfloat16 g_ch[MTOT*DD];
__device__ __nv_bfloat16 g_cl[MTOT*DD];
__device__ float g_part[2*LRS*BB*RR*DD];
__device__ __nv_bfloat16 g_xEh[BB*RR*DD];
__device__ __nv_bfloat16 g_xEl[BB*RR*DD];
__device__ __nv_bfloat16 g_xFh[BB*RR*DD];
__device__ __nv_bfloat16 g_xFl[BB*RR*DD];
__device__ float g_Klow[BB*RR*DD];
__device__ float g_Vlow[BB*RR*DD];

// ---------------------------------------------------------------------------
// helpers
// ---------------------------------------------------------------------------
__device__ __forceinline__ uint32_t smem_u32(const void* p) {
    uint32_t a;
    asm("{ .reg .u64 t; cvta.to.shared.u64 t, %1; cvt.u32.u64 %0, t; }" : "=r"(a) : "l"(p));
    return a;
}
__device__ __forceinline__ uint32_t swz(uint32_t off) {
    return off ^ ((off >> 3) & 0x70);   // SW128
}
__device__ __forceinline__ void cpasync16(uint32_t saddr, const void* g) {
    asm volatile("cp.async.cg.shared.global [%0], [%1], 16;" :: "r"(saddr), "l"(g) : "memory");
}
__device__ __forceinline__ void ldsm4(uint32_t* d, uint32_t addr) {
    asm volatile("ldmatrix.sync.aligned.m8n8.x4.shared.b16 {%0,%1,%2,%3}, [%4];"
        : "=r"(d[0]), "=r"(d[1]), "=r"(d[2]), "=r"(d[3]) : "r"(addr));
}
__device__ __forceinline__ void mma16816(float* c, const uint32_t* a, const uint32_t* b) {
    asm volatile("mma.sync.aligned.m16n8k16.row.col.f32.bf16.bf16.f32 "
        "{%0,%1,%2,%3}, {%4,%5,%6,%7}, {%8,%9}, {%0,%1,%2,%3};"
        : "+f"(c[0]), "+f"(c[1]), "+f"(c[2]), "+f"(c[3])
        : "r"(a[0]), "r"(a[1]), "r"(a[2]), "r"(a[3]), "r"(b[0]), "r"(b[1]));
}

// ---------------------------------------------------------------------------
// fp32 -> (bf16 hi, bf16 lo) split (x) — used per half
// ---------------------------------------------------------------------------
__global__ void cvt_split(const float* __restrict__ in, __nv_bfloat16* __restrict__ hi,
                          __nv_bfloat16* __restrict__ lo, int n4)
{
    int i = blockIdx.x * blockDim.x + threadIdx.x;
    if (i >= n4) return;
    float4 v = ((const float4*)in)[i];
    float f[4] = {v.x, v.y, v.z, v.w};
    unsigned short hs[4], ls[4];
#pragma unroll
    for (int j = 0; j < 4; j++) {
        __nv_bfloat16 hb = __float2bfloat16(f[j]);
        __nv_bfloat16 lb = __float2bfloat16(f[j] - __bfloat162float(hb));
        hs[j] = __bfloat16_as_ushort(hb);
        ls[j] = __bfloat16_as_ushort(lb);
    }
    ushort4 h = {hs[0], hs[1], hs[2], hs[3]};
    ushort4 l = {ls[0], ls[1], ls[2], ls[3]};
    ((ushort4*)hi)[i] = h;
    ((ushort4*)lo)[i] = l;
}

// all four weights in one launch: blockIdx.y selects the weight
__global__ void cvt_split4(const float* __restrict__ w0, const float* __restrict__ w1,
                           const float* __restrict__ w2, const float* __restrict__ w3,
                           __nv_bfloat16* __restrict__ hi, __nv_bfloat16* __restrict__ lo)
{
    const int wsel = blockIdx.y;
    const float* in = (wsel == 0) ? w0 : (wsel == 1) ? w1 : (wsel == 2) ? w2 : w3;
    int i = blockIdx.x * blockDim.x + threadIdx.x;
    if (i >= DD*DD/4) return;
    float4 v = ((const float4*)in)[i];
    float f[4] = {v.x, v.y, v.z, v.w};
    unsigned short hs[4], ls[4];
#pragma unroll
    for (int j = 0; j < 4; j++) {
        __nv_bfloat16 hb = __float2bfloat16(f[j]);
        __nv_bfloat16 lb = __float2bfloat16(f[j] - __bfloat162float(hb));
        hs[j] = __bfloat16_as_ushort(hb);
        ls[j] = __bfloat16_as_ushort(lb);
    }
    ushort4 h = {hs[0], hs[1], hs[2], hs[3]};
    ushort4 l = {ls[0], ls[1], ls[2], ls[3]};
    ((ushort4*)(hi + (size_t)wsel * DD * DD))[i] = h;
    ((ushort4*)(lo + (size_t)wsel * DD * DD))[i] = l;
}

// zero both accumulators in one launch
__global__ void zero2_f32(float* __restrict__ p0, float* __restrict__ p1, int n4)
{
    int i = blockIdx.x * blockDim.x + threadIdx.x;
    float4 z = {0.f, 0.f, 0.f, 0.f};
    if (i < n4) ((float4*)p0)[i] = z;
    else if (i < 2*n4) ((float4*)p1)[i - n4] = z;
}

// ---------------------------------------------------------------------------
// Split-bf16 mma.sync GEMM: C[m,n'] = sum_k A[m,k]*B[n',k] (+bias)
//   128x128 tile, BK=64, 8 warps (warp tile 64x32), 3-stage cp.async pipeline.
//   m_base: row offset (for half-GEMM launches).
// ---------------------------------------------------------------------------
#define STAGE_B 65536
#define SMEM_GEMM (3*STAGE_B + 1024)

__global__ __launch_bounds__(256, 1)
void gemm_split(const __nv_bfloat16* __restrict__ Ah, const __nv_bfloat16* __restrict__ Al,
                const __nv_bfloat16* __restrict__ Bh, const __nv_bfloat16* __restrict__ Bl,
                float* __restrict__ C, const float* __restrict__ bias, int m_base)
{
    extern __shared__ char smem_raw[];
    char* sm = (char*)((((uintptr_t)smem_raw) + 1023) & ~(uintptr_t)1023);
    const uint32_t sb = smem_u32(sm);

    const int tid  = threadIdx.x;
    const int wid  = tid >> 5;
    const int lane = tid & 31;
    const int m0 = m_base + blockIdx.y * 128;
    const int n0 = blockIdx.x * 128;
    const int wm = (wid & 1) * 64;
    const int wn = (wid >> 1) * 32;

    float acc[4][4][4];
#pragma unroll
    for (int a = 0; a < 4; a++)
#pragma unroll
        for (int b = 0; b < 4; b++)
#pragma unroll
            for (int e = 0; e < 4; e++) acc[a][b][e] = 0.0f;

#define LOAD_STAGE(kc, s) do { \
        const uint32_t st_ = sb + (s) * STAGE_B; \
        const int k0_ = (kc) * 64; \
        _Pragma("unroll") \
        for (int t4 = 0; t4 < 4; t4++) { \
            const int q = tid + t4 * 256; \
            const int r = q >> 3; \
            const int c = q & 7; \
            const uint32_t sw = swz((uint32_t)(r * 128 + c * 16)); \
            const size_t aoff = (size_t)(m0 + r) * DD + k0_ + c * 8; \
            const size_t boff = (size_t)(n0 + r) * DD + k0_ + c * 8; \
            cpasync16(st_ +         sw, Ah + aoff); \
            cpasync16(st_ + 16384 + sw, Al + aoff); \
            cpasync16(st_ + 32768 + sw, Bh + boff); \
            cpasync16(st_ + 49152 + sw, Bl + boff); \
        } \
    } while (0)

    LOAD_STAGE(0, 0);
    asm volatile("cp.async.commit_group;" ::: "memory");
    LOAD_STAGE(1, 1);
    asm volatile("cp.async.commit_group;" ::: "memory");

    const int arow  = lane & 15;
    const int acb   = (lane >> 4) * 16;
    const int brow2 = (lane >> 4) * 8 + (lane & 7);
    const int bhalf = ((lane >> 3) & 1) * 16;

    for (int kc = 0; kc < 16; kc++) {
        if (kc >= 14) asm volatile("cp.async.wait_group 0;" ::: "memory");
        else          asm volatile("cp.async.wait_group 1;" ::: "memory");
        __syncthreads();
        if (kc + 2 < 16) {
            LOAD_STAGE(kc + 2, (kc + 2) % 3);
            asm volatile("cp.async.commit_group;" ::: "memory");
        }

        const uint32_t st = sb + (kc % 3) * STAGE_B;
#pragma unroll
        for (int ks = 0; ks < 4; ks++) {
            uint32_t ah[4][4], al[4][4], bh[8], bl[8];
#pragma unroll
            for (int mf = 0; mf < 4; mf++) {
                const uint32_t off = swz((uint32_t)((wm + mf * 16 + arow) * 128 + ks * 32 + acb));
                ldsm4(ah[mf], st + off);
                ldsm4(al[mf], st + 16384 + off);
            }
#pragma unroll
            for (int p = 0; p < 2; p++) {
                const uint32_t off = swz((uint32_t)((wn + p * 16 + brow2) * 128 + ks * 32 + bhalf));
                ldsm4(&bh[p * 4], st + 32768 + off);
                ldsm4(&bl[p * 4], st + 49152 + off);
            }
#pragma unroll
            for (int mf = 0; mf < 4; mf++)
#pragma unroll
                for (int nf = 0; nf < 4; nf++) {
                    mma16816(acc[mf][nf], ah[mf], &bh[nf * 2]);
                    mma16816(acc[mf][nf], ah[mf], &bl[nf * 2]);
                    mma16816(acc[mf][nf], al[mf], &bh[nf * 2]);
                }
        }
    }
    __syncthreads();

    // ---- epilogue: regs -> smem -> coalesced gmem ----
    float* sf = (float*)sm;
    const int rr = lane >> 2;
    const int cc = (lane & 3) * 2;
#pragma unroll
    for (int mf = 0; mf < 4; mf++)
#pragma unroll
        for (int nf = 0; nf < 4; nf++)
#pragma unroll
            for (int e = 0; e < 4; e++) {
                const int row = wm + mf * 16 + rr + ((e & 2) ? 8 : 0);
                const int col = wn + nf * 8 + cc + (e & 1);
                sf[row * 132 + col] = acc[mf][nf][e];
            }
    __syncthreads();

    for (int t = tid; t < 128 * 32; t += 256) {
        const int r  = t >> 5;
        const int c4 = (t & 31) << 2;
        float4 v;
        v.x = sf[r * 132 + c4 + 0];
        v.y = sf[r * 132 + c4 + 1];
        v.z = sf[r * 132 + c4 + 2];
        v.w = sf[r * 132 + c4 + 3];
        if (bias) {
            v.x += bias[n0 + c4 + 0];
            v.y += bias[n0 + c4 + 1];
            v.z += bias[n0 + c4 + 2];
            v.w += bias[n0 + c4 + 3];
        }
        *(float4*)(C + (size_t)(m0 + r) * DD + n0 + c4) = v;
    }
#undef LOAD_STAGE
}

// ---------------------------------------------------------------------------
// Split-K small GEMM (M=256): one launch covers both Klow and Vlow.
// ---------------------------------------------------------------------------
#define STAGE_S 65536
#define SMEM_SMALL (2*STAGE_S + 1024)

__global__ __launch_bounds__(256, 1)
void gemm_splitk(const __nv_bfloat16* __restrict__ xEh, const __nv_bfloat16* __restrict__ xEl,
                 const __nv_bfloat16* __restrict__ xFh, const __nv_bfloat16* __restrict__ xFl,
                 const __nv_bfloat16* __restrict__ Wh,  const __nv_bfloat16* __restrict__ Wl,
                 float* __restrict__ Klow, float* __restrict__ Vlow)
{
    extern __shared__ char smem_raw[];
    char* sm = (char*)((((uintptr_t)smem_raw) + 1023) & ~(uintptr_t)1023);
    const uint32_t sb = smem_u32(sm);

    const int tid  = threadIdx.x;
    const int wid  = tid >> 5;
    const int lane = tid & 31;
    const int m0 = blockIdx.y * 128;
    const int n0 = blockIdx.x * 128;
    const int pair = blockIdx.z >> 3;
    const int ksp  = blockIdx.z & 7;
    const int wm = (wid & 1) * 64;
    const int wn = (wid >> 1) * 32;

    const __nv_bfloat16* Ah = pair ? xFh : xEh;
    const __nv_bfloat16* Al = pair ? xFl : xEl;
    const __nv_bfloat16* Bh = Wh + (size_t)(pair ? 2 : 1) * DD * DD;
    const __nv_bfloat16* Bl = Wl + (size_t)(pair ? 2 : 1) * DD * DD;
    float* C = pair ? Vlow : Klow;

    float acc[4][4][4];
#pragma unroll
    for (int a = 0; a < 4; a++)
#pragma unroll
        for (int b = 0; b < 4; b++)
#pragma unroll
            for (int e = 0; e < 4; e++) acc[a][b][e] = 0.0f;

#define LOAD_STAGE_S(kc, s) do { \
        const uint32_t st_ = sb + (s) * STAGE_S; \
        const int k0_ = (kc) * 64; \
        _Pragma("unroll") \
        for (int t4 = 0; t4 < 4; t4++) { \
            const int q = tid + t4 * 256; \
            const int r = q >> 3; \
            const int c = q & 7; \
            const uint32_t sw = swz((uint32_t)(r * 128 + c * 16)); \
            const size_t aoff = (size_t)(m0 + r) * DD + k0_ + c * 8; \
            const size_t boff = (size_t)(n0 + r) * DD + k0_ + c * 8; \
            cpasync16(st_ +         sw, Ah + aoff); \
            cpasync16(st_ + 16384 + sw, Al + aoff); \
            cpasync16(st_ + 32768 + sw, Bh + boff); \
            cpasync16(st_ + 49152 + sw, Bl + boff); \
        } \
    } while (0)

    const int kc0 = ksp * 2;
    LOAD_STAGE_S(kc0, 0);
    asm volatile("cp.async.commit_group;" ::: "memory");
    LOAD_STAGE_S(kc0 + 1, 1);
    asm volatile("cp.async.commit_group;" ::: "memory");

    const int arow  = lane & 15;
    const int acb   = (lane >> 4) * 16;
    const int brow2 = (lane >> 4) * 8 + (lane & 7);
    const int bhalf = ((lane >> 3) & 1) * 16;

#pragma unroll
    for (int it = 0; it < 2; it++) {
        if (it == 0) asm volatile("cp.async.wait_group 1;" ::: "memory");
        else         asm volatile("cp.async.wait_group 0;" ::: "memory");
        __syncthreads();
        const uint32_t st = sb + it * STAGE_S;
#pragma unroll
        for (int ks = 0; ks < 4; ks++) {
            uint32_t ah[4][4], al[4][4], bh[8], bl[8];
#pragma unroll
            for (int mf = 0; mf < 4; mf++) {
                const uint32_t off = swz((uint32_t)((wm + mf * 16 + arow) * 128 + ks * 32 + acb));
                ldsm4(ah[mf], st + off);
                ldsm4(al[mf], st + 16384 + off);
            }
#pragma unroll
            for (int p = 0; p < 2; p++) {
                const uint32_t off = swz((uint32_t)((wn + p * 16 + brow2) * 128 + ks * 32 + bhalf));
                ldsm4(&bh[p * 4], st + 32768 + off);
                ldsm4(&bl[p * 4], st + 49152 + off);
            }
#pragma unroll
            for (int mf = 0; mf < 4; mf++)
#pragma unroll
                for (int nf = 0; nf < 4; nf++) {
                    mma16816(acc[mf][nf], ah[mf], &bh[nf * 2]);
                    mma16816(acc[mf][nf], ah[mf], &bl[nf * 2]);
                    mma16816(acc[mf][nf], al[mf], &bh[nf * 2]);
                }
        }
    }
    __syncthreads();

    float* sf = (float*)sm;
    const int rr = lane >> 2;
    const int cc = (lane & 3) * 2;
#pragma unroll
    for (int mf = 0; mf < 4; mf++)
#pragma unroll
        for (int nf = 0; nf < 4; nf++)
#pragma unroll
            for (int e = 0; e < 4; e++) {
                const int row = wm + mf * 16 + rr + ((e & 2) ? 8 : 0);
                const int col = wn + nf * 8 + cc + (e & 1);
                sf[row * 132 + col] = acc[mf][nf][e];
            }
    __syncthreads();

    for (int t = tid; t < 128 * 32; t += 256) {
        const int r  = t >> 5;
        const int c4 = (t & 31) << 2;
        float* cp = C + (size_t)(m0 + r) * DD + n0 + c4;
        atomicAdd(cp + 0, sf[r * 132 + c4 + 0]);
        atomicAdd(cp + 1, sf[r * 132 + c4 + 1]);
        atomicAdd(cp + 2, sf[r * 132 + c4 + 2]);
        atomicAdd(cp + 3, sf[r * 132 + c4 + 3]);
    }
#undef LOAD_STAGE_S
}

// ---------------------------------------------------------------------------
// Low-rank on x:  partE[sp][b][r][d] = sum_{n in slice} E[n,r]*x[b,n,d]
// ---------------------------------------------------------------------------
__global__ __launch_bounds__(256, 4)
void lowrank_x(const float* __restrict__ x, const float* __restrict__ E,
               const float* __restrict__ Fm, float* __restrict__ part)
{
    const int b  = blockIdx.y >> 3;
    const int sp = blockIdx.y & 7;
    const int d0 = blockIdx.x * 64;

    __shared__ float Es[32][64];
    __shared__ float Fs[32][64];
    __shared__ float Xs[32][64];

    const int tid = threadIdx.x;
    const int r0 = (tid >> 4) << 2;
    const int c0 = (tid & 15) << 2;

    float accE[4][4], accF[4][4];
#pragma unroll
    for (int i = 0; i < 4; i++)
#pragma unroll
        for (int j = 0; j < 4; j++) { accE[i][j] = 0.0f; accF[i][j] = 0.0f; }

    const int nbeg = sp * (NN / LRS);

    for (int nt = 0; nt < (NN / LRS); nt += 32) {
        const int n0 = nbeg + nt;
        for (int i = tid; i < 512; i += 256) {
            const int row  = i >> 4;
            const int col4 = (i & 15) << 2;
            *(float4*)&Es[row][col4] = *(const float4*)(E  + (size_t)(n0 + row) * RR + col4);
            *(float4*)&Fs[row][col4] = *(const float4*)(Fm + (size_t)(n0 + row) * RR + col4);
            *(float4*)&Xs[row][col4] = *(const float4*)(x + ((size_t)b * NN + n0 + row) * DD + d0 + col4);
        }
        __syncthreads();
#pragma unroll 8
        for (int nn = 0; nn < 32; nn++) {
            float ae[4], af[4], xv[4];
#pragma unroll
            for (int i = 0; i < 4; i++) { ae[i] = Es[nn][r0 + i]; af[i] = Fs[nn][r0 + i]; }
#pragma unroll
            for (int j = 0; j < 4; j++) xv[j] = Xs[nn][c0 + j];
#pragma unroll
            for (int i = 0; i < 4; i++)
#pragma unroll
                for (int j = 0; j < 4; j++) {
                    accE[i][j] = fmaf(ae[i], xv[j], accE[i][j]);
                    accF[i][j] = fmaf(af[i], xv[j], accF[i][j]);
                }
        }
        __syncthreads();
    }

    float* OE = part + ((size_t)(0 * LRS + sp) * BB + b) * RR * DD;
    float* OF = part + ((size_t)(1 * LRS + sp) * BB + b) * RR * DD;
#pragma unroll
    for (int i = 0; i < 4; i++) {
        float4 ve = {accE[i][0], accE[i][1], accE[i][2], accE[i][3]};
        float4 vf = {accF[i][0], accF[i][1], accF[i][2], accF[i][3]};
        *(float4*)(OE + (size_t)(r0 + i) * DD + d0 + c0) = ve;
        *(float4*)(OF + (size_t)(r0 + i) * DD + d0 + c0) = vf;
    }
}

// reduce partials and emit bf16 hi/lo splits for the small GEMMs
__global__ void lr_reduce_split(const float* __restrict__ part,
                                __nv_bfloat16* __restrict__ xEh, __nv_bfloat16* __restrict__ xEl,
                                __nv_bfloat16* __restrict__ xFh, __nv_bfloat16* __restrict__ xFl)
{
    const int ELEMS = BB * RR * DD;  // 262144
    int i = blockIdx.x * blockDim.x + threadIdx.x;
    if (i >= 2 * ELEMS) return;
    const int pair = (i >= ELEMS);
    const int j = i - pair * ELEMS;
    const float* p = part + (size_t)pair * LRS * ELEMS;
    float s = 0.0f;
#pragma unroll
    for (int sp = 0; sp < LRS; sp++) s += p[(size_t)sp * ELEMS + j];
    __nv_bfloat16 hb = __float2bfloat16(s);
    __nv_bfloat16 lb = __float2bfloat16(s - __bfloat162float(hb));
    if (pair) { xFh[j] = hb; xFl[j] = lb; }
    else      { xEh[j] = hb; xEl[j] = lb; }
}

// ---------------------------------------------------------------------------
// Attention: scores = Q.Klow/8, softmax over R=64 (bounded: no max-sub),
// ctx written as bf16 (hi, lo) split.  b_base: batch offset for half launches.
// ---------------------------------------------------------------------------
__global__ __launch_bounds__(256, 4)
void linformer_attn(const float* __restrict__ Q, const float* __restrict__ Klow,
                    const float* __restrict__ Vlow,
                    __nv_bfloat16* __restrict__ ctx_hi, __nv_bfloat16* __restrict__ ctx_lo,
                    int b_base)
{
    const int b  = b_base + blockIdx.z;
    const int h  = blockIdx.y;
    const int n0 = blockIdx.x * 64;

    __shared__ float Ks[64][65];
    __shared__ float Vs[64][64];

    const int tid = threadIdx.x;
    for (int i = tid; i < 1024; i += 256) {
        const int r  = i >> 4;
        const int c4 = (i & 15) << 2;
        float4 kv = *(const float4*)(Klow + ((size_t)(b * RR + r)) * DD + h * HDIM + c4);
        Ks[r][c4 + 0] = kv.x; Ks[r][c4 + 1] = kv.y;
        Ks[r][c4 + 2] = kv.z; Ks[r][c4 + 3] = kv.w;
        float4 vv = *(const float4*)(Vlow + ((size_t)(b * RR + r)) * DD + h * HDIM + c4);
        *(float4*)&Vs[r][c4] = vv;
    }
    __syncthreads();

    const int warp = tid >> 5;
    const int lane = tid & 31;

    for (int rr = 0; rr < 8; rr++) {
        const int n = n0 + warp * 8 + rr;
        const float* qp = Q + ((size_t)(b * NN + n)) * DD + h * HDIM;
        const float q0 = qp[lane];
        const float q1 = qp[lane + 32];

        float s0 = 0.0f, s1 = 0.0f;
#pragma unroll
        for (int hd = 0; hd < 64; hd++) {
            float qv = __shfl_sync(0xffffffffu, (hd < 32) ? q0 : q1, hd & 31);
            s0 = fmaf(qv, Ks[lane][hd],      s0);
            s1 = fmaf(qv, Ks[lane + 32][hd], s1);
        }
        float e0 = __expf(s0 * 0.125f);
        float e1 = __expf(s1 * 0.125f);
        float sum = e0 + e1;
#pragma unroll
        for (int off = 16; off > 0; off >>= 1)
            sum += __shfl_xor_sync(0xffffffffu, sum, off);
        const float inv = 1.0f / sum;
        const float a0 = e0 * inv;
        const float a1 = e1 * inv;

        float o0 = 0.0f, o1 = 0.0f;
#pragma unroll
        for (int r = 0; r < 64; r++) {
            float av = __shfl_sync(0xffffffffu, (r < 32) ? a0 : a1, r & 31);
            o0 = fmaf(av, Vs[r][lane],      o0);
            o1 = fmaf(av, Vs[r][lane + 32], o1);
        }
        const size_t base = ((size_t)(b * NN + n)) * DD + h * HDIM;
        __nv_bfloat16 h0 = __float2bfloat16(o0);
        __nv_bfloat16 h1 = __float2bfloat16(o1);
        ctx_hi[base + lane]      = h0;
        ctx_hi[base + lane + 32] = h1;
        ctx_lo[base + lane]      = __float2bfloat16(o0 - __bfloat162float(h0));
        ctx_lo[base + lane + 32] = __float2bfloat16(o1 - __bfloat162float(h1));
    }
}

// ---------------------------------------------------------------------------
extern "C" void kernel_launch(void* const* d_in, const int* in_sizes, int n_in,
                              void* d_out, int out_size)
{
    const float* x  = (const float*)d_in[0];
    const float* Wq = (const float*)d_in[1];
    const float* Wk = (const float*)d_in[2];
    const float* Wv = (const float*)d_in[3];
    const float* Wo = (const float*)d_in[4];
    const float* bo = (const float*)d_in[5];
    const float* E  = (const float*)d_in[6];
    const float* Fm = (const float*)d_in[7];
    float* out = (float*)d_out;

    __nv_bfloat16 *xh, *xl, *wh, *wl, *ch, *cl, *xEh, *xEl, *xFh, *xFl;
    float *q, *kl, *vl, *part;
    cudaGetSymbolAddress((void**)&xh, g_xh);
    cudaGetSymbolAddress((void**)&xl, g_xl);
    cudaGetSymbolAddress((void**)&wh, g_Wh);
    cudaGetSymbolAddress((void**)&wl, g_Wl);
    cudaGetSymbolAddress((void**)&q,  g_Q);
    cudaGetSymbolAddress((void**)&ch, g_ch);
    cudaGetSymbolAddress((void**)&cl, g_cl);
    cudaGetSymbolAddress((void**)&part, g_part);
    cudaGetSymbolAddress((void**)&xEh, g_xEh);
    cudaGetSymbolAddress((void**)&xEl, g_xEl);
    cudaGetSymbolAddress((void**)&xFh, g_xFh);
    cudaGetSymbolAddress((void**)&xFl, g_xFl);
    cudaGetSymbolAddress((void**)&kl, g_Klow);
    cudaGetSymbolAddress((void**)&vl, g_Vlow);

    cudaFuncSetAttribute(gemm_split,  cudaFuncAttributeMaxDynamicSharedMemorySize, SMEM_GEMM);
    cudaFuncSetAttribute(gemm_splitk, cudaFuncAttributeMaxDynamicSharedMemorySize, SMEM_SMALL);

    // persistent streams/events (created once; identical enqueue each call)
    static cudaStream_t s1 = nullptr, s2 = nullptr;
    static cudaEvent_t eFork = nullptr, eW = nullptr, eJoin = nullptr, eXb = nullptr,
                       eQa = nullptr, eQb = nullptr, eAa = nullptr, eAb = nullptr,
                       eOa = nullptr;
    if (s1 == nullptr) {
        cudaStreamCreateWithFlags(&s1, cudaStreamNonBlocking);
        cudaStreamCreateWithFlags(&s2, cudaStreamNonBlocking);
        cudaEventCreateWithFlags(&eFork, cudaEventDisableTiming);
        cudaEventCreateWithFlags(&eW,    cudaEventDisableTiming);
        cudaEventCreateWithFlags(&eJoin, cudaEventDisableTiming);
        cudaEventCreateWithFlags(&eXb,   cudaEventDisableTiming);
        cudaEventCreateWithFlags(&eQa,   cudaEventDisableTiming);
        cudaEventCreateWithFlags(&eQb,   cudaEventDisableTiming);
        cudaEventCreateWithFlags(&eAa,   cudaEventDisableTiming);
        cudaEventCreateWithFlags(&eAb,   cudaEventDisableTiming);
        cudaEventCreateWithFlags(&eOa,   cudaEventDisableTiming);
    }

    const size_t WO = 3*(size_t)DD*DD;

    // ---- fork ----
    cudaEventRecord(eFork, 0);
    cudaStreamWaitEvent(s1, eFork, 0);
    cudaStreamWaitEvent(s2, eFork, 0);

    // s1: low-rank side chain (reads only raw inputs)
    zero2_f32<<<(2*BB*RR*DD/4 + 255)/256, 256, 0, s1>>>(kl, vl, BB*RR*DD/4);
    lowrank_x<<<dim3(DD/64, BB*LRS), 256, 0, s1>>>(x, E, Fm, part);
    lr_reduce_split<<<(2*BB*RR*DD + 255)/256, 256, 0, s1>>>(part, xEh, xEl, xFh, xFl);

    // s2: x second-half cvt (hides under QG_a)
    cvt_split<<<(MHALF*DD/4 + 255)/256, 256, 0, s2>>>(
        x + (size_t)MHALF*DD, xh + (size_t)MHALF*DD, xl + (size_t)MHALF*DD, MHALF*DD/4);
    cudaEventRecord(eXb, s2);

    // main: weight cvt; then s1's splitk may read wh/wl
    cvt_split4<<<dim3((DD*DD/4 + 255)/256, 4), 256>>>(Wq, Wk, Wv, Wo, wh, wl);
    cudaEventRecord(eW, 0);
    cudaStreamWaitEvent(s1, eW, 0);
    gemm_splitk<<<dim3(DD/128, 2, 16), 256, SMEM_SMALL, s1>>>(
        xEh, xEl, xFh, xFl, wh, wl, kl, vl);
    cudaEventRecord(eJoin, s1);

    // main: x first-half cvt + QG_a (batches 0,1)
    cvt_split<<<(MHALF*DD/4 + 255)/256, 256>>>(x, xh, xl, MHALF*DD/4);
    gemm_split<<<dim3(DD/128, MHALF/128), 256, SMEM_GEMM>>>(
        xh, xl, wh, wl, q, nullptr, 0);
    cudaEventRecord(eQa, 0);

    // main: QG_b (batches 2,3) — needs s2's cvt of x's second half
    cudaStreamWaitEvent(0, eXb, 0);
    gemm_split<<<dim3(DD/128, MHALF/128), 256, SMEM_GEMM>>>(
        xh, xl, wh, wl, q, nullptr, MHALF);
    cudaEventRecord(eQb, 0);

    // s2: attn_a (needs QG_a + Klow/Vlow) — overlaps QG_b
    cudaStreamWaitEvent(s2, eQa, 0);
    cudaStreamWaitEvent(s2, eJoin, 0);
    linformer_attn<<<dim3(NN/64, HH, 2), 256, 0, s2>>>(q, kl, vl, ch, cl, 0);
    cudaEventRecord(eAa, s2);

    // s2: attn_b (needs QG_b)
    cudaStreamWaitEvent(s2, eQb, 0);
    linformer_attn<<<dim3(NN/64, HH, 2), 256, 0, s2>>>(q, kl, vl, ch, cl, 2);
    cudaEventRecord(eAb, s2);

    // s1: OG_a (needs only attn_a) — overlaps QG_b's tail
    cudaStreamWaitEvent(s1, eAa, 0);
    gemm_split<<<dim3(DD/128, MHALF/128), 256, SMEM_GEMM, s1>>>(
        ch, cl, wh + WO, wl + WO, out, bo, 0);
    cudaEventRecord(eOa, s1);

    // main: OG_b (after QG_b in stream order; needs attn_b)
    cudaStreamWaitEvent(0, eAb, 0);
    gemm_split<<<dim3(DD/128, MHALF/128), 256, SMEM_GEMM>>>(
        ch, cl, wh + WO, wl + WO, out, bo, MHALF);

    // final join
    cudaStreamWaitEvent(0, eOa, 0);
}

// round 16
// speedup vs baseline: 1.0041x; 1.0041x over previous
#include <cuda_runtime.h>
#include <cuda_bf16.h>
#include <cstdint>
#include <math.h>

#define BB 4
#define NN 4096
#define DD 1024
#define HH 16
#define RR 64
#define HDIM 64
#define MTOT (BB*NN)   // 16384
#define LRS 8          // lowrank N-split

// ---------------------------------------------------------------------------
// Scratch (device globals — no allocation allowed)
// ---------------------------------------------------------------------------
__device__ __nv_bfloat16 g_xh[MTOT*DD];
__device__ __nv_bfloat16 g_xl[MTOT*DD];
__device__ __nv_bfloat16 g_Wh[4*DD*DD];   // 0=Wq 1=Wk 2=Wv 3=Wo
__device__ __nv_bfloat16 g_Wl[4*DD*DD];
__device__ float g_Q[MTOT*DD];
__device__ __nv_bfloat16 g_ch[MTOT*DD];
__device__ __nv_bfloat16 g_cl[MTOT*DD];
__device__ float g_part[2*LRS*BB*RR*DD];
__device__ __nv_bfloat16 g_xEh[BB*RR*DD];
__device__ __nv_bfloat16 g_xEl[BB*RR*DD];
__device__ __nv_bfloat16 g_xFh[BB*RR*DD];
__device__ __nv_bfloat16 g_xFl[BB*RR*DD];
__device__ float g_Klow[BB*RR*DD];
__device__ float g_Vlow[BB*RR*DD];

// ---------------------------------------------------------------------------
// helpers
// ---------------------------------------------------------------------------
__device__ __forceinline__ uint32_t smem_u32(const void* p) {
    uint32_t a;
    asm("{ .reg .u64 t; cvta.to.shared.u64 t, %1; cvt.u32.u64 %0, t; }" : "=r"(a) : "l"(p));
    return a;
}
__device__ __forceinline__ uint32_t swz(uint32_t off) {
    return off ^ ((off >> 3) & 0x70);   // SW128
}
__device__ __forceinline__ void cpasync16(uint32_t saddr, const void* g) {
    asm volatile("cp.async.cg.shared.global [%0], [%1], 16;" :: "r"(saddr), "l"(g) : "memory");
}
__device__ __forceinline__ void ldsm4(uint32_t* d, uint32_t addr) {
    asm volatile("ldmatrix.sync.aligned.m8n8.x4.shared.b16 {%0,%1,%2,%3}, [%4];"
        : "=r"(d[0]), "=r"(d[1]), "=r"(d[2]), "=r"(d[3]) : "r"(addr));
}
__device__ __forceinline__ void mma16816(float* c, const uint32_t* a, const uint32_t* b) {
    asm volatile("mma.sync.aligned.m16n8k16.row.col.f32.bf16.bf16.f32 "
        "{%0,%1,%2,%3}, {%4,%5,%6,%7}, {%8,%9}, {%0,%1,%2,%3};"
        : "+f"(c[0]), "+f"(c[1]), "+f"(c[2]), "+f"(c[3])
        : "r"(a[0]), "r"(a[1]), "r"(a[2]), "r"(a[3]), "r"(b[0]), "r"(b[1]));
}

// ---------------------------------------------------------------------------
// fp32 -> (bf16 hi, bf16 lo) split (x)
// ---------------------------------------------------------------------------
__global__ void cvt_split(const float* __restrict__ in, __nv_bfloat16* __restrict__ hi,
                          __nv_bfloat16* __restrict__ lo, int n4)
{
    int i = blockIdx.x * blockDim.x + threadIdx.x;
    if (i >= n4) return;
    float4 v = ((const float4*)in)[i];
    float f[4] = {v.x, v.y, v.z, v.w};
    unsigned short hs[4], ls[4];
#pragma unroll
    for (int j = 0; j < 4; j++) {
        __nv_bfloat16 hb = __float2bfloat16(f[j]);
        __nv_bfloat16 lb = __float2bfloat16(f[j] - __bfloat162float(hb));
        hs[j] = __bfloat16_as_ushort(hb);
        ls[j] = __bfloat16_as_ushort(lb);
    }
    ushort4 h = {hs[0], hs[1], hs[2], hs[3]};
    ushort4 l = {ls[0], ls[1], ls[2], ls[3]};
    ((ushort4*)hi)[i] = h;
    ((ushort4*)lo)[i] = l;
}

// all four weights in one launch: blockIdx.y selects the weight
__global__ void cvt_split4(const float* __restrict__ w0, const float* __restrict__ w1,
                           const float* __restrict__ w2, const float* __restrict__ w3,
                           __nv_bfloat16* __restrict__ hi, __nv_bfloat16* __restrict__ lo)
{
    const int wsel = blockIdx.y;
    const float* in = (wsel == 0) ? w0 : (wsel == 1) ? w1 : (wsel == 2) ? w2 : w3;
    int i = blockIdx.x * blockDim.x + threadIdx.x;
    if (i >= DD*DD/4) return;
    float4 v = ((const float4*)in)[i];
    float f[4] = {v.x, v.y, v.z, v.w};
    unsigned short hs[4], ls[4];
#pragma unroll
    for (int j = 0; j < 4; j++) {
        __nv_bfloat16 hb = __float2bfloat16(f[j]);
        __nv_bfloat16 lb = __float2bfloat16(f[j] - __bfloat162float(hb));
        hs[j] = __bfloat16_as_ushort(hb);
        ls[j] = __bfloat16_as_ushort(lb);
    }
    ushort4 h = {hs[0], hs[1], hs[2], hs[3]};
    ushort4 l = {ls[0], ls[1], ls[2], ls[3]};
    ((ushort4*)(hi + (size_t)wsel * DD * DD))[i] = h;
    ((ushort4*)(lo + (size_t)wsel * DD * DD))[i] = l;
}

// zero both accumulators in one launch
__global__ void zero2_f32(float* __restrict__ p0, float* __restrict__ p1, int n4)
{
    int i = blockIdx.x * blockDim.x + threadIdx.x;
    float4 z = {0.f, 0.f, 0.f, 0.f};
    if (i < n4) ((float4*)p0)[i] = z;
    else if (i < 2*n4) ((float4*)p1)[i - n4] = z;
}

// ---------------------------------------------------------------------------
// Split-bf16 mma.sync GEMM: C[m,n'] = sum_k A[m,k]*B[n',k] (+bias)
//   256x128 CTA tile, BK=64, 8 warps (warp tile 64x64), 2-stage cp.async.
//   Stage: Ah 32K | Al 32K | Bh 16K | Bl 16K = 96KB
// ---------------------------------------------------------------------------
#define STAGE_B 98304
#define SMEM_GEMM (2*STAGE_B + 1024)

__global__ __launch_bounds__(256, 1)
void gemm_split(const __nv_bfloat16* __restrict__ Ah, const __nv_bfloat16* __restrict__ Al,
                const __nv_bfloat16* __restrict__ Bh, const __nv_bfloat16* __restrict__ Bl,
                float* __restrict__ C, const float* __restrict__ bias)
{
    extern __shared__ char smem_raw[];
    char* sm = (char*)((((uintptr_t)smem_raw) + 1023) & ~(uintptr_t)1023);
    const uint32_t sb = smem_u32(sm);

    const int tid  = threadIdx.x;
    const int wid  = tid >> 5;
    const int lane = tid & 31;
    const int m0 = blockIdx.y * 256;
    const int n0 = blockIdx.x * 128;
    const int wm = (wid & 3) * 64;      // 4 m-warps
    const int wn = (wid >> 2) * 64;     // 2 n-warps

    float acc[4][8][4];
#pragma unroll
    for (int a = 0; a < 4; a++)
#pragma unroll
        for (int b = 0; b < 8; b++)
#pragma unroll
            for (int e = 0; e < 4; e++) acc[a][b][e] = 0.0f;

#define LOAD_STAGE(kc, s) do { \
        const uint32_t st_ = sb + (s) * STAGE_B; \
        const int k0_ = (kc) * 64; \
        _Pragma("unroll") \
        for (int i = 0; i < 8; i++) { \
            const int q = tid + i * 256; \
            const int r = q >> 3; \
            const int c = q & 7; \
            const uint32_t sw = swz((uint32_t)(r * 128 + c * 16)); \
            const size_t aoff = (size_t)(m0 + r) * DD + k0_ + c * 8; \
            cpasync16(st_ +         sw, Ah + aoff); \
            cpasync16(st_ + 32768 + sw, Al + aoff); \
        } \
        _Pragma("unroll") \
        for (int i = 0; i < 4; i++) { \
            const int q = tid + i * 256; \
            const int r = q >> 3; \
            const int c = q & 7; \
            const uint32_t sw = swz((uint32_t)(r * 128 + c * 16)); \
            const size_t boff = (size_t)(n0 + r) * DD + k0_ + c * 8; \
            cpasync16(st_ + 65536 + sw, Bh + boff); \
            cpasync16(st_ + 81920 + sw, Bl + boff); \
        } \
    } while (0)

    LOAD_STAGE(0, 0);
    asm volatile("cp.async.commit_group;" ::: "memory");

    const int arow  = lane & 15;
    const int acb   = (lane >> 4) * 16;
    const int brow2 = (lane >> 4) * 8 + (lane & 7);
    const int bhalf = ((lane >> 3) & 1) * 16;

    for (int kc = 0; kc < 16; kc++) {
        if (kc + 1 < 16) {
            LOAD_STAGE(kc + 1, (kc + 1) & 1);
            asm volatile("cp.async.commit_group;" ::: "memory");
            asm volatile("cp.async.wait_group 1;" ::: "memory");
        } else {
            asm volatile("cp.async.wait_group 0;" ::: "memory");
        }
        __syncthreads();

        const uint32_t st = sb + (kc & 1) * STAGE_B;
#pragma unroll
        for (int ks = 0; ks < 4; ks++) {
            uint32_t ah[4][4], al[4][4];
#pragma unroll
            for (int mf = 0; mf < 4; mf++) {
                const uint32_t off = swz((uint32_t)((wm + mf * 16 + arow) * 128 + ks * 32 + acb));
                ldsm4(ah[mf], st + off);
                ldsm4(al[mf], st + 32768 + off);
            }
#pragma unroll
            for (int h2 = 0; h2 < 2; h2++) {
                uint32_t bh[8], bl[8];
#pragma unroll
                for (int bp = 0; bp < 2; bp++) {
                    const uint32_t off = swz((uint32_t)((wn + h2 * 32 + bp * 16 + brow2) * 128 + ks * 32 + bhalf));
                    ldsm4(&bh[bp * 4], st + 65536 + off);
                    ldsm4(&bl[bp * 4], st + 81920 + off);
                }
#pragma unroll
                for (int mf = 0; mf < 4; mf++)
#pragma unroll
                    for (int nf = 0; nf < 4; nf++) {
                        float* c = acc[mf][h2 * 4 + nf];
                        mma16816(c, ah[mf], &bh[nf * 2]);
                        mma16816(c, ah[mf], &bl[nf * 2]);
                        mma16816(c, al[mf], &bh[nf * 2]);
                    }
            }
        }
        __syncthreads();
    }

    // ---- epilogue: regs -> smem (256x132 f32) -> coalesced gmem ----
    float* sf = (float*)sm;
    const int rr = lane >> 2;
    const int cc = (lane & 3) * 2;
#pragma unroll
    for (int mf = 0; mf < 4; mf++)
#pragma unroll
        for (int nf = 0; nf < 8; nf++)
#pragma unroll
            for (int e = 0; e < 4; e++) {
                const int row = wm + mf * 16 + rr + ((e & 2) ? 8 : 0);
                const int col = wn + nf * 8 + cc + (e & 1);
                sf[row * 132 + col] = acc[mf][nf][e];
            }
    __syncthreads();

    for (int t = tid; t < 256 * 32; t += 256) {
        const int r  = t >> 5;
        const int c4 = (t & 31) << 2;
        float4 v;
        v.x = sf[r * 132 + c4 + 0];
        v.y = sf[r * 132 + c4 + 1];
        v.z = sf[r * 132 + c4 + 2];
        v.w = sf[r * 132 + c4 + 3];
        if (bias) {
            v.x += bias[n0 + c4 + 0];
            v.y += bias[n0 + c4 + 1];
            v.z += bias[n0 + c4 + 2];
            v.w += bias[n0 + c4 + 3];
        }
        *(float4*)(C + (size_t)(m0 + r) * DD + n0 + c4) = v;
    }
#undef LOAD_STAGE
}

// ---------------------------------------------------------------------------
// Split-K small GEMM (M=256): one launch covers both Klow and Vlow.
// grid (8, 2, 16): z = pair*8 + ksplit; K slice of 128 per CTA.
// ---------------------------------------------------------------------------
#define STAGE_S 65536
#define SMEM_SMALL (2*STAGE_S + 1024)

__global__ __launch_bounds__(256, 1)
void gemm_splitk(const __nv_bfloat16* __restrict__ xEh, const __nv_bfloat16* __restrict__ xEl,
                 const __nv_bfloat16* __restrict__ xFh, const __nv_bfloat16* __restrict__ xFl,
                 const __nv_bfloat16* __restrict__ Wh,  const __nv_bfloat16* __restrict__ Wl,
                 float* __restrict__ Klow, float* __restrict__ Vlow)
{
    extern __shared__ char smem_raw[];
    char* sm = (char*)((((uintptr_t)smem_raw) + 1023) & ~(uintptr_t)1023);
    const uint32_t sb = smem_u32(sm);

    const int tid  = threadIdx.x;
    const int wid  = tid >> 5;
    const int lane = tid & 31;
    const int m0 = blockIdx.y * 128;
    const int n0 = blockIdx.x * 128;
    const int pair = blockIdx.z >> 3;
    const int ksp  = blockIdx.z & 7;
    const int wm = (wid & 1) * 64;
    const int wn = (wid >> 1) * 32;

    const __nv_bfloat16* Ah = pair ? xFh : xEh;
    const __nv_bfloat16* Al = pair ? xFl : xEl;
    const __nv_bfloat16* Bh = Wh + (size_t)(pair ? 2 : 1) * DD * DD;
    const __nv_bfloat16* Bl = Wl + (size_t)(pair ? 2 : 1) * DD * DD;
    float* C = pair ? Vlow : Klow;

    float acc[4][4][4];
#pragma unroll
    for (int a = 0; a < 4; a++)
#pragma unroll
        for (int b = 0; b < 4; b++)
#pragma unroll
            for (int e = 0; e < 4; e++) acc[a][b][e] = 0.0f;

#define LOAD_STAGE_S(kc, s) do { \
        const uint32_t st_ = sb + (s) * STAGE_S; \
        const int k0_ = (kc) * 64; \
        _Pragma("unroll") \
        for (int t4 = 0; t4 < 4; t4++) { \
            const int q = tid + t4 * 256; \
            const int r = q >> 3; \
            const int c = q & 7; \
            const uint32_t sw = swz((uint32_t)(r * 128 + c * 16)); \
            const size_t aoff = (size_t)(m0 + r) * DD + k0_ + c * 8; \
            const size_t boff = (size_t)(n0 + r) * DD + k0_ + c * 8; \
            cpasync16(st_ +         sw, Ah + aoff); \
            cpasync16(st_ + 16384 + sw, Al + aoff); \
            cpasync16(st_ + 32768 + sw, Bh + boff); \
            cpasync16(st_ + 49152 + sw, Bl + boff); \
        } \
    } while (0)

    const int kc0 = ksp * 2;
    LOAD_STAGE_S(kc0, 0);
    asm volatile("cp.async.commit_group;" ::: "memory");
    LOAD_STAGE_S(kc0 + 1, 1);
    asm volatile("cp.async.commit_group;" ::: "memory");

    const int arow  = lane & 15;
    const int acb   = (lane >> 4) * 16;
    const int brow2 = (lane >> 4) * 8 + (lane & 7);
    const int bhalf = ((lane >> 3) & 1) * 16;

#pragma unroll
    for (int it = 0; it < 2; it++) {
        if (it == 0) asm volatile("cp.async.wait_group 1;" ::: "memory");
        else         asm volatile("cp.async.wait_group 0;" ::: "memory");
        __syncthreads();
        const uint32_t st = sb + it * STAGE_S;
#pragma unroll
        for (int ks = 0; ks < 4; ks++) {
            uint32_t ah[4][4], al[4][4], bh[8], bl[8];
#pragma unroll
            for (int mf = 0; mf < 4; mf++) {
                const uint32_t off = swz((uint32_t)((wm + mf * 16 + arow) * 128 + ks * 32 + acb));
                ldsm4(ah[mf], st + off);
                ldsm4(al[mf], st + 16384 + off);
            }
#pragma unroll
            for (int p = 0; p < 2; p++) {
                const uint32_t off = swz((uint32_t)((wn + p * 16 + brow2) * 128 + ks * 32 + bhalf));
                ldsm4(&bh[p * 4], st + 32768 + off);
                ldsm4(&bl[p * 4], st + 49152 + off);
            }
#pragma unroll
            for (int mf = 0; mf < 4; mf++)
#pragma unroll
                for (int nf = 0; nf < 4; nf++) {
                    mma16816(acc[mf][nf], ah[mf], &bh[nf * 2]);
                    mma16816(acc[mf][nf], ah[mf], &bl[nf * 2]);
                    mma16816(acc[mf][nf], al[mf], &bh[nf * 2]);
                }
        }
    }
    __syncthreads();

    float* sf = (float*)sm;
    const int rr = lane >> 2;
    const int cc = (lane & 3) * 2;
#pragma unroll
    for (int mf = 0; mf < 4; mf++)
#pragma unroll
        for (int nf = 0; nf < 4; nf++)
#pragma unroll
            for (int e = 0; e < 4; e++) {
                const int row = wm + mf * 16 + rr + ((e & 2) ? 8 : 0);
                const int col = wn + nf * 8 + cc + (e & 1);
                sf[row * 132 + col] = acc[mf][nf][e];
            }
    __syncthreads();

    for (int t = tid; t < 128 * 32; t += 256) {
        const int r  = t >> 5;
        const int c4 = (t & 31) << 2;
        float* cp = C + (size_t)(m0 + r) * DD + n0 + c4;
        atomicAdd(cp + 0, sf[r * 132 + c4 + 0]);
        atomicAdd(cp + 1, sf[r * 132 + c4 + 1]);
        atomicAdd(cp + 2, sf[r * 132 + c4 + 2]);
        atomicAdd(cp + 3, sf[r * 132 + c4 + 3]);
    }
#undef LOAD_STAGE_S
}

// ---------------------------------------------------------------------------
// Low-rank on x:  partE[sp][b][r][d] = sum_{n in slice} E[n,r]*x[b,n,d]
// ---------------------------------------------------------------------------
__global__ __launch_bounds__(256, 4)
void lowrank_x(const float* __restrict__ x, const float* __restrict__ E,
               const float* __restrict__ Fm, float* __restrict__ part)
{
    const int b  = blockIdx.y >> 3;
    const int sp = blockIdx.y & 7;
    const int d0 = blockIdx.x * 64;

    __shared__ float Es[32][64];
    __shared__ float Fs[32][64];
    __shared__ float Xs[32][64];

    const int tid = threadIdx.x;
    const int r0 = (tid >> 4) << 2;
    const int c0 = (tid & 15) << 2;

    float accE[4][4], accF[4][4];
#pragma unroll
    for (int i = 0; i < 4; i++)
#pragma unroll
        for (int j = 0; j < 4; j++) { accE[i][j] = 0.0f; accF[i][j] = 0.0f; }

    const int nbeg = sp * (NN / LRS);

    for (int nt = 0; nt < (NN / LRS); nt += 32) {
        const int n0 = nbeg + nt;
        for (int i = tid; i < 512; i += 256) {
            const int row  = i >> 4;
            const int col4 = (i & 15) << 2;
            *(float4*)&Es[row][col4] = *(const float4*)(E  + (size_t)(n0 + row) * RR + col4);
            *(float4*)&Fs[row][col4] = *(const float4*)(Fm + (size_t)(n0 + row) * RR + col4);
            *(float4*)&Xs[row][col4] = *(const float4*)(x + ((size_t)b * NN + n0 + row) * DD + d0 + col4);
        }
        __syncthreads();
#pragma unroll 8
        for (int nn = 0; nn < 32; nn++) {
            float ae[4], af[4], xv[4];
#pragma unroll
            for (int i = 0; i < 4; i++) { ae[i] = Es[nn][r0 + i]; af[i] = Fs[nn][r0 + i]; }
#pragma unroll
            for (int j = 0; j < 4; j++) xv[j] = Xs[nn][c0 + j];
#pragma unroll
            for (int i = 0; i < 4; i++)
#pragma unroll
                for (int j = 0; j < 4; j++) {
                    accE[i][j] = fmaf(ae[i], xv[j], accE[i][j]);
                    accF[i][j] = fmaf(af[i], xv[j], accF[i][j]);
                }
        }
        __syncthreads();
    }

    float* OE = part + ((size_t)(0 * LRS + sp) * BB + b) * RR * DD;
    float* OF = part + ((size_t)(1 * LRS + sp) * BB + b) * RR * DD;
#pragma unroll
    for (int i = 0; i < 4; i++) {
        float4 ve = {accE[i][0], accE[i][1], accE[i][2], accE[i][3]};
        float4 vf = {accF[i][0], accF[i][1], accF[i][2], accF[i][3]};
        *(float4*)(OE + (size_t)(r0 + i) * DD + d0 + c0) = ve;
        *(float4*)(OF + (size_t)(r0 + i) * DD + d0 + c0) = vf;
    }
}

// reduce partials and emit bf16 hi/lo splits for the small GEMMs
__global__ void lr_reduce_split(const float* __restrict__ part,
                                __nv_bfloat16* __restrict__ xEh, __nv_bfloat16* __restrict__ xEl,
                                __nv_bfloat16* __restrict__ xFh, __nv_bfloat16* __restrict__ xFl)
{
    const int ELEMS = BB * RR * DD;  // 262144
    int i = blockIdx.x * blockDim.x + threadIdx.x;
    if (i >= 2 * ELEMS) return;
    const int pair = (i >= ELEMS);
    const int j = i - pair * ELEMS;
    const float* p = part + (size_t)pair * LRS * ELEMS;
    float s = 0.0f;
#pragma unroll
    for (int sp = 0; sp < LRS; sp++) s += p[(size_t)sp * ELEMS + j];
    __nv_bfloat16 hb = __float2bfloat16(s);
    __nv_bfloat16 lb = __float2bfloat16(s - __bfloat162float(hb));
    if (pair) { xFh[j] = hb; xFl[j] = lb; }
    else      { xEh[j] = hb; xEl[j] = lb; }
}

// ---------------------------------------------------------------------------
// Attention: scores = Q.Klow/8, softmax over R=64 (bounded: no max-sub),
// ctx written as bf16 (hi, lo) split
// ---------------------------------------------------------------------------
__global__ __launch_bounds__(256, 4)
void linformer_attn(const float* __restrict__ Q, const float* __restrict__ Klow,
                    const float* __restrict__ Vlow,
                    __nv_bfloat16* __restrict__ ctx_hi, __nv_bfloat16* __restrict__ ctx_lo)
{
    const int b  = blockIdx.z;
    const int h  = blockIdx.y;
    const int n0 = blockIdx.x * 64;

    __shared__ float Ks[64][65];
    __shared__ float Vs[64][64];

    const int tid = threadIdx.x;
    for (int i = tid; i < 1024; i += 256) {
        const int r  = i >> 4;
        const int c4 = (i & 15) << 2;
        float4 kv = *(const float4*)(Klow + ((size_t)(b * RR + r)) * DD + h * HDIM + c4);
        Ks[r][c4 + 0] = kv.x; Ks[r][c4 + 1] = kv.y;
        Ks[r][c4 + 2] = kv.z; Ks[r][c4 + 3] = kv.w;
        float4 vv = *(const float4*)(Vlow + ((size_t)(b * RR + r)) * DD + h * HDIM + c4);
        *(float4*)&Vs[r][c4] = vv;
    }
    __syncthreads();

    const int warp = tid >> 5;
    const int lane = tid & 31;

    for (int rr = 0; rr < 8; rr++) {
        const int n = n0 + warp * 8 + rr;
        const float* qp = Q + ((size_t)(b * NN + n)) * DD + h * HDIM;
        const float q0 = qp[lane];
        const float q1 = qp[lane + 32];

        float s0 = 0.0f, s1 = 0.0f;
#pragma unroll
        for (int hd = 0; hd < 64; hd++) {
            float qv = __shfl_sync(0xffffffffu, (hd < 32) ? q0 : q1, hd & 31);
            s0 = fmaf(qv, Ks[lane][hd],      s0);
            s1 = fmaf(qv, Ks[lane + 32][hd], s1);
        }
        float e0 = __expf(s0 * 0.125f);
        float e1 = __expf(s1 * 0.125f);
        float sum = e0 + e1;
#pragma unroll
        for (int off = 16; off > 0; off >>= 1)
            sum += __shfl_xor_sync(0xffffffffu, sum, off);
        const float inv = 1.0f / sum;
        const float a0 = e0 * inv;
        const float a1 = e1 * inv;

        float o0 = 0.0f, o1 = 0.0f;
#pragma unroll
        for (int r = 0; r < 64; r++) {
            float av = __shfl_sync(0xffffffffu, (r < 32) ? a0 : a1, r & 31);
            o0 = fmaf(av, Vs[r][lane],      o0);
            o1 = fmaf(av, Vs[r][lane + 32], o1);
        }
        const size_t base = ((size_t)(b * NN + n)) * DD + h * HDIM;
        __nv_bfloat16 h0 = __float2bfloat16(o0);
        __nv_bfloat16 h1 = __float2bfloat16(o1);
        ctx_hi[base + lane]      = h0;
        ctx_hi[base + lane + 32] = h1;
        ctx_lo[base + lane]      = __float2bfloat16(o0 - __bfloat162float(h0));
        ctx_lo[base + lane + 32] = __float2bfloat16(o1 - __bfloat162float(h1));
    }
}

// ---------------------------------------------------------------------------
extern "C" void kernel_launch(void* const* d_in, const int* in_sizes, int n_in,
                              void* d_out, int out_size)
{
    const float* x  = (const float*)d_in[0];
    const float* Wq = (const float*)d_in[1];
    const float* Wk = (const float*)d_in[2];
    const float* Wv = (const float*)d_in[3];
    const float* Wo = (const float*)d_in[4];
    const float* bo = (const float*)d_in[5];
    const float* E  = (const float*)d_in[6];
    const float* Fm = (const float*)d_in[7];
    float* out = (float*)d_out;

    __nv_bfloat16 *xh, *xl, *wh, *wl, *ch, *cl, *xEh, *xEl, *xFh, *xFl;
    float *q, *kl, *vl, *part;
    cudaGetSymbolAddress((void**)&xh, g_xh);
    cudaGetSymbolAddress((void**)&xl, g_xl);
    cudaGetSymbolAddress((void**)&wh, g_Wh);
    cudaGetSymbolAddress((void**)&wl, g_Wl);
    cudaGetSymbolAddress((void**)&q,  g_Q);
    cudaGetSymbolAddress((void**)&ch, g_ch);
    cudaGetSymbolAddress((void**)&cl, g_cl);
    cudaGetSymbolAddress((void**)&part, g_part);
    cudaGetSymbolAddress((void**)&xEh, g_xEh);
    cudaGetSymbolAddress((void**)&xEl, g_xEl);
    cudaGetSymbolAddress((void**)&xFh, g_xFh);
    cudaGetSymbolAddress((void**)&xFl, g_xFl);
    cudaGetSymbolAddress((void**)&kl, g_Klow);
    cudaGetSymbolAddress((void**)&vl, g_Vlow);

    cudaFuncSetAttribute(gemm_split,  cudaFuncAttributeMaxDynamicSharedMemorySize, SMEM_GEMM);
    cudaFuncSetAttribute(gemm_splitk, cudaFuncAttributeMaxDynamicSharedMemorySize, SMEM_SMALL);

    // persistent side-stream + events (created once; identical enqueue each call)
    static cudaStream_t s1 = nullptr;
    static cudaEvent_t eFork = nullptr, eW = nullptr, eJoin = nullptr;
    if (s1 == nullptr) {
        cudaStreamCreateWithFlags(&s1, cudaStreamNonBlocking);
        cudaEventCreateWithFlags(&eFork, cudaEventDisableTiming);
        cudaEventCreateWithFlags(&eW,    cudaEventDisableTiming);
        cudaEventCreateWithFlags(&eJoin, cudaEventDisableTiming);
    }

    // ---- fork: Klow/Vlow chain on s1 (reads only raw inputs until splitk) ----
    cudaEventRecord(eFork, 0);
    cudaStreamWaitEvent(s1, eFork, 0);

    zero2_f32<<<(2*BB*RR*DD/4 + 255)/256, 256, 0, s1>>>(kl, vl, BB*RR*DD/4);
    lowrank_x<<<dim3(DD/64, BB*LRS), 256, 0, s1>>>(x, E, Fm, part);
    lr_reduce_split<<<(2*BB*RR*DD + 255)/256, 256, 0, s1>>>(part, xEh, xEl, xFh, xFl);

    // ---- main: weight cvt; record eW so s1's splitk safely reads wh/wl ----
    cvt_split4<<<dim3((DD*DD/4 + 255)/256, 4), 256>>>(Wq, Wk, Wv, Wo, wh, wl);
    cudaEventRecord(eW, 0);
    cudaStreamWaitEvent(s1, eW, 0);

    gemm_splitk<<<dim3(DD/128, 2, 16), 256, SMEM_SMALL, s1>>>(
        xEh, xEl, xFh, xFl, wh, wl, kl, vl);
    cudaEventRecord(eJoin, s1);

    // ---- main: x cvt + Q projection (256x128 tiles) ----
    cvt_split<<<(MTOT*DD/4 + 255)/256, 256>>>(x, xh, xl, MTOT*DD/4);
    gemm_split<<<dim3(DD/128, MTOT/256), 256, SMEM_GEMM>>>(
        xh, xl, wh + 0*(size_t)DD*DD, wl + 0*(size_t)DD*DD, q, nullptr);

    // ---- join: attention needs Q + Klow/Vlow ----
    cudaStreamWaitEvent(0, eJoin, 0);

    linformer_attn<<<dim3(NN/64, HH, BB), 256>>>(q, kl, vl, ch, cl);

    gemm_split<<<dim3(DD/128, MTOT/256), 256, SMEM_GEMM>>>(
        ch, cl, wh + 3*(size_t)DD*DD, wl + 3*(size_t)DD*DD, out, bo);
}

// round 17
// speedup vs baseline: 1.1859x; 1.1810x over previous
#include <cuda_runtime.h>
#include <cuda_fp16.h>
#include <cstdint>
#include <math.h>

#define BB 4
#define NN 4096
#define DD 1024
#define HH 16
#define RR 64
#define HDIM 64
#define MTOT (BB*NN)   // 16384
#define LRS 8          // lowrank N-split

// ---------------------------------------------------------------------------
// Scratch (device globals — no allocation allowed)
// ---------------------------------------------------------------------------
__device__ __half g_xh[MTOT*DD];          // x as single fp16
__device__ __half g_Wh[4*DD*DD];          // weight hi (0=Wq 1=Wk 2=Wv 3=Wo)
__device__ __half g_Wl[4*DD*DD];          // weight lo
__device__ float  g_Q[MTOT*DD];
__device__ __half g_ch[MTOT*DD];          // ctx as single fp16
__device__ float  g_part[2*LRS*BB*RR*DD];
__device__ __half g_xEh[BB*RR*DD];
__device__ __half g_xEl[BB*RR*DD];
__device__ __half g_xFh[BB*RR*DD];
__device__ __half g_xFl[BB*RR*DD];
__device__ float  g_Klow[BB*RR*DD];
__device__ float  g_Vlow[BB*RR*DD];

// ---------------------------------------------------------------------------
// helpers
// ---------------------------------------------------------------------------
__device__ __forceinline__ uint32_t smem_u32(const void* p) {
    uint32_t a;
    asm("{ .reg .u64 t; cvta.to.shared.u64 t, %1; cvt.u32.u64 %0, t; }" : "=r"(a) : "l"(p));
    return a;
}
__device__ __forceinline__ uint32_t swz(uint32_t off) {
    return off ^ ((off >> 3) & 0x70);   // SW128
}
__device__ __forceinline__ void cpasync16(uint32_t saddr, const void* g) {
    asm volatile("cp.async.cg.shared.global [%0], [%1], 16;" :: "r"(saddr), "l"(g) : "memory");
}
__device__ __forceinline__ void ldsm4(uint32_t* d, uint32_t addr) {
    asm volatile("ldmatrix.sync.aligned.m8n8.x4.shared.b16 {%0,%1,%2,%3}, [%4];"
        : "=r"(d[0]), "=r"(d[1]), "=r"(d[2]), "=r"(d[3]) : "r"(addr));
}
__device__ __forceinline__ void mma16816(float* c, const uint32_t* a, const uint32_t* b) {
    asm volatile("mma.sync.aligned.m16n8k16.row.col.f32.f16.f16.f32 "
        "{%0,%1,%2,%3}, {%4,%5,%6,%7}, {%8,%9}, {%0,%1,%2,%3};"
        : "+f"(c[0]), "+f"(c[1]), "+f"(c[2]), "+f"(c[3])
        : "r"(a[0]), "r"(a[1]), "r"(a[2]), "r"(a[3]), "r"(b[0]), "r"(b[1]));
}

// ---------------------------------------------------------------------------
// fp32 -> single fp16 (activations)
// ---------------------------------------------------------------------------
__global__ void cvt_h(const float* __restrict__ in, __half* __restrict__ hi, int n4)
{
    int i = blockIdx.x * blockDim.x + threadIdx.x;
    if (i >= n4) return;
    float4 v = ((const float4*)in)[i];
    ushort4 h;
    h.x = __half_as_ushort(__float2half(v.x));
    h.y = __half_as_ushort(__float2half(v.y));
    h.z = __half_as_ushort(__float2half(v.z));
    h.w = __half_as_ushort(__float2half(v.w));
    ((ushort4*)hi)[i] = h;
}

// all four weights: fp16 hi/lo split, one launch
__global__ void cvt_w4(const float* __restrict__ w0, const float* __restrict__ w1,
                       const float* __restrict__ w2, const float* __restrict__ w3,
                       __half* __restrict__ hi, __half* __restrict__ lo)
{
    const int wsel = blockIdx.y;
    const float* in = (wsel == 0) ? w0 : (wsel == 1) ? w1 : (wsel == 2) ? w2 : w3;
    int i = blockIdx.x * blockDim.x + threadIdx.x;
    if (i >= DD*DD/4) return;
    float4 v = ((const float4*)in)[i];
    float f[4] = {v.x, v.y, v.z, v.w};
    unsigned short hs[4], ls[4];
#pragma unroll
    for (int j = 0; j < 4; j++) {
        __half hb = __float2half(f[j]);
        __half lb = __float2half(f[j] - __half2float(hb));
        hs[j] = __half_as_ushort(hb);
        ls[j] = __half_as_ushort(lb);
    }
    ushort4 h = {hs[0], hs[1], hs[2], hs[3]};
    ushort4 l = {ls[0], ls[1], ls[2], ls[3]};
    ((ushort4*)(hi + (size_t)wsel * DD * DD))[i] = h;
    ((ushort4*)(lo + (size_t)wsel * DD * DD))[i] = l;
}

// zero both accumulators in one launch
__global__ void zero2_f32(float* __restrict__ p0, float* __restrict__ p1, int n4)
{
    int i = blockIdx.x * blockDim.x + threadIdx.x;
    float4 z = {0.f, 0.f, 0.f, 0.f};
    if (i < n4) ((float4*)p0)[i] = z;
    else if (i < 2*n4) ((float4*)p1)[i - n4] = z;
}

// ---------------------------------------------------------------------------
// 2-pass fp16 GEMM: C[m,n'] = sum_k A[m,k]*(Bh[n',k]+Bl[n',k]) (+bias)
//   A single fp16, B 2-term fp16 split. 128x128 tile, BK=64, 8 warps (64x32),
//   3-stage cp.async. Stage: A 16K | Bh 16K | Bl 16K = 48KB.
// ---------------------------------------------------------------------------
#define STAGE_B 49152
#define SMEM_GEMM (3*STAGE_B + 1024)

__global__ __launch_bounds__(256, 1)
void gemm2p(const __half* __restrict__ A, const __half* __restrict__ Bh,
            const __half* __restrict__ Bl,
            float* __restrict__ C, const float* __restrict__ bias)
{
    extern __shared__ char smem_raw[];
    char* sm = (char*)((((uintptr_t)smem_raw) + 1023) & ~(uintptr_t)1023);
    const uint32_t sb = smem_u32(sm);

    const int tid  = threadIdx.x;
    const int wid  = tid >> 5;
    const int lane = tid & 31;
    const int m0 = blockIdx.y * 128;
    const int n0 = blockIdx.x * 128;
    const int wm = (wid & 1) * 64;
    const int wn = (wid >> 1) * 32;

    float acc[4][4][4];
#pragma unroll
    for (int a = 0; a < 4; a++)
#pragma unroll
        for (int b = 0; b < 4; b++)
#pragma unroll
            for (int e = 0; e < 4; e++) acc[a][b][e] = 0.0f;

#define LOAD_STAGE(kc, s) do { \
        const uint32_t st_ = sb + (s) * STAGE_B; \
        const int k0_ = (kc) * 64; \
        _Pragma("unroll") \
        for (int t4 = 0; t4 < 4; t4++) { \
            const int q = tid + t4 * 256; \
            const int r = q >> 3; \
            const int c = q & 7; \
            const uint32_t sw = swz((uint32_t)(r * 128 + c * 16)); \
            const size_t aoff = (size_t)(m0 + r) * DD + k0_ + c * 8; \
            const size_t boff = (size_t)(n0 + r) * DD + k0_ + c * 8; \
            cpasync16(st_ +         sw, A  + aoff); \
            cpasync16(st_ + 16384 + sw, Bh + boff); \
            cpasync16(st_ + 32768 + sw, Bl + boff); \
        } \
    } while (0)

    LOAD_STAGE(0, 0);
    asm volatile("cp.async.commit_group;" ::: "memory");
    LOAD_STAGE(1, 1);
    asm volatile("cp.async.commit_group;" ::: "memory");

    const int arow  = lane & 15;
    const int acb   = (lane >> 4) * 16;
    const int brow2 = (lane >> 4) * 8 + (lane & 7);
    const int bhalf = ((lane >> 3) & 1) * 16;

    for (int kc = 0; kc < 16; kc++) {
        if (kc >= 14) asm volatile("cp.async.wait_group 0;" ::: "memory");
        else          asm volatile("cp.async.wait_group 1;" ::: "memory");
        __syncthreads();
        if (kc + 2 < 16) {
            LOAD_STAGE(kc + 2, (kc + 2) % 3);
            asm volatile("cp.async.commit_group;" ::: "memory");
        }

        const uint32_t st = sb + (kc % 3) * STAGE_B;
#pragma unroll
        for (int ks = 0; ks < 4; ks++) {
            uint32_t ah[4][4], bh[8], bl[8];
#pragma unroll
            for (int mf = 0; mf < 4; mf++) {
                const uint32_t off = swz((uint32_t)((wm + mf * 16 + arow) * 128 + ks * 32 + acb));
                ldsm4(ah[mf], st + off);
            }
#pragma unroll
            for (int p = 0; p < 2; p++) {
                const uint32_t off = swz((uint32_t)((wn + p * 16 + brow2) * 128 + ks * 32 + bhalf));
                ldsm4(&bh[p * 4], st + 16384 + off);
                ldsm4(&bl[p * 4], st + 32768 + off);
            }
#pragma unroll
            for (int mf = 0; mf < 4; mf++)
#pragma unroll
                for (int nf = 0; nf < 4; nf++) {
                    mma16816(acc[mf][nf], ah[mf], &bh[nf * 2]);
                    mma16816(acc[mf][nf], ah[mf], &bl[nf * 2]);
                }
        }
    }
    __syncthreads();

    // ---- epilogue: regs -> smem -> coalesced gmem ----
    float* sf = (float*)sm;
    const int rr = lane >> 2;
    const int cc = (lane & 3) * 2;
#pragma unroll
    for (int mf = 0; mf < 4; mf++)
#pragma unroll
        for (int nf = 0; nf < 4; nf++)
#pragma unroll
            for (int e = 0; e < 4; e++) {
                const int row = wm + mf * 16 + rr + ((e & 2) ? 8 : 0);
                const int col = wn + nf * 8 + cc + (e & 1);
                sf[row * 132 + col] = acc[mf][nf][e];
            }
    __syncthreads();

    for (int t = tid; t < 128 * 32; t += 256) {
        const int r  = t >> 5;
        const int c4 = (t & 31) << 2;
        float4 v;
        v.x = sf[r * 132 + c4 + 0];
        v.y = sf[r * 132 + c4 + 1];
        v.z = sf[r * 132 + c4 + 2];
        v.w = sf[r * 132 + c4 + 3];
        if (bias) {
            v.x += bias[n0 + c4 + 0];
            v.y += bias[n0 + c4 + 1];
            v.z += bias[n0 + c4 + 2];
            v.w += bias[n0 + c4 + 3];
        }
        *(float4*)(C + (size_t)(m0 + r) * DD + n0 + c4) = v;
    }
#undef LOAD_STAGE
}

// ---------------------------------------------------------------------------
// Split-K small GEMM (M=256), 3-pass fp16 (full accuracy; off critical path).
// grid (8, 2, 16): z = pair*8 + ksplit; K slice of 128 per CTA.
// ---------------------------------------------------------------------------
#define STAGE_S 65536
#define SMEM_SMALL (2*STAGE_S + 1024)

__global__ __launch_bounds__(256, 1)
void gemm_splitk(const __half* __restrict__ xEh, const __half* __restrict__ xEl,
                 const __half* __restrict__ xFh, const __half* __restrict__ xFl,
                 const __half* __restrict__ Wh,  const __half* __restrict__ Wl,
                 float* __restrict__ Klow, float* __restrict__ Vlow)
{
    extern __shared__ char smem_raw[];
    char* sm = (char*)((((uintptr_t)smem_raw) + 1023) & ~(uintptr_t)1023);
    const uint32_t sb = smem_u32(sm);

    const int tid  = threadIdx.x;
    const int wid  = tid >> 5;
    const int lane = tid & 31;
    const int m0 = blockIdx.y * 128;
    const int n0 = blockIdx.x * 128;
    const int pair = blockIdx.z >> 3;
    const int ksp  = blockIdx.z & 7;
    const int wm = (wid & 1) * 64;
    const int wn = (wid >> 1) * 32;

    const __half* Ah = pair ? xFh : xEh;
    const __half* Al = pair ? xFl : xEl;
    const __half* Bh = Wh + (size_t)(pair ? 2 : 1) * DD * DD;
    const __half* Bl = Wl + (size_t)(pair ? 2 : 1) * DD * DD;
    float* C = pair ? Vlow : Klow;

    float acc[4][4][4];
#pragma unroll
    for (int a = 0; a < 4; a++)
#pragma unroll
        for (int b = 0; b < 4; b++)
#pragma unroll
            for (int e = 0; e < 4; e++) acc[a][b][e] = 0.0f;

#define LOAD_STAGE_S(kc, s) do { \
        const uint32_t st_ = sb + (s) * STAGE_S; \
        const int k0_ = (kc) * 64; \
        _Pragma("unroll") \
        for (int t4 = 0; t4 < 4; t4++) { \
            const int q = tid + t4 * 256; \
            const int r = q >> 3; \
            const int c = q & 7; \
            const uint32_t sw = swz((uint32_t)(r * 128 + c * 16)); \
            const size_t aoff = (size_t)(m0 + r) * DD + k0_ + c * 8; \
            const size_t boff = (size_t)(n0 + r) * DD + k0_ + c * 8; \
            cpasync16(st_ +         sw, Ah + aoff); \
            cpasync16(st_ + 16384 + sw, Al + aoff); \
            cpasync16(st_ + 32768 + sw, Bh + boff); \
            cpasync16(st_ + 49152 + sw, Bl + boff); \
        } \
    } while (0)

    const int kc0 = ksp * 2;
    LOAD_STAGE_S(kc0, 0);
    asm volatile("cp.async.commit_group;" ::: "memory");
    LOAD_STAGE_S(kc0 + 1, 1);
    asm volatile("cp.async.commit_group;" ::: "memory");

    const int arow  = lane & 15;
    const int acb   = (lane >> 4) * 16;
    const int brow2 = (lane >> 4) * 8 + (lane & 7);
    const int bhalf = ((lane >> 3) & 1) * 16;

#pragma unroll
    for (int it = 0; it < 2; it++) {
        if (it == 0) asm volatile("cp.async.wait_group 1;" ::: "memory");
        else         asm volatile("cp.async.wait_group 0;" ::: "memory");
        __syncthreads();
        const uint32_t st = sb + it * STAGE_S;
#pragma unroll
        for (int ks = 0; ks < 4; ks++) {
            uint32_t ah[4][4], al[4][4], bh[8], bl[8];
#pragma unroll
            for (int mf = 0; mf < 4; mf++) {
                const uint32_t off = swz((uint32_t)((wm + mf * 16 + arow) * 128 + ks * 32 + acb));
                ldsm4(ah[mf], st + off);
                ldsm4(al[mf], st + 16384 + off);
            }
#pragma unroll
            for (int p = 0; p < 2; p++) {
                const uint32_t off = swz((uint32_t)((wn + p * 16 + brow2) * 128 + ks * 32 + bhalf));
                ldsm4(&bh[p * 4], st + 32768 + off);
                ldsm4(&bl[p * 4], st + 49152 + off);
            }
#pragma unroll
            for (int mf = 0; mf < 4; mf++)
#pragma unroll
                for (int nf = 0; nf < 4; nf++) {
                    mma16816(acc[mf][nf], ah[mf], &bh[nf * 2]);
                    mma16816(acc[mf][nf], ah[mf], &bl[nf * 2]);
                    mma16816(acc[mf][nf], al[mf], &bh[nf * 2]);
                }
        }
    }
    __syncthreads();

    float* sf = (float*)sm;
    const int rr = lane >> 2;
    const int cc = (lane & 3) * 2;
#pragma unroll
    for (int mf = 0; mf < 4; mf++)
#pragma unroll
        for (int nf = 0; nf < 4; nf++)
#pragma unroll
            for (int e = 0; e < 4; e++) {
                const int row = wm + mf * 16 + rr + ((e & 2) ? 8 : 0);
                const int col = wn + nf * 8 + cc + (e & 1);
                sf[row * 132 + col] = acc[mf][nf][e];
            }
    __syncthreads();

    for (int t = tid; t < 128 * 32; t += 256) {
        const int r  = t >> 5;
        const int c4 = (t & 31) << 2;
        float* cp = C + (size_t)(m0 + r) * DD + n0 + c4;
        atomicAdd(cp + 0, sf[r * 132 + c4 + 0]);
        atomicAdd(cp + 1, sf[r * 132 + c4 + 1]);
        atomicAdd(cp + 2, sf[r * 132 + c4 + 2]);
        atomicAdd(cp + 3, sf[r * 132 + c4 + 3]);
    }
#undef LOAD_STAGE_S
}

// ---------------------------------------------------------------------------
// Low-rank on x:  partE[sp][b][r][d] = sum_{n in slice} E[n,r]*x[b,n,d]
// ---------------------------------------------------------------------------
__global__ __launch_bounds__(256, 4)
void lowrank_x(const float* __restrict__ x, const float* __restrict__ E,
               const float* __restrict__ Fm, float* __restrict__ part)
{
    const int b  = blockIdx.y >> 3;
    const int sp = blockIdx.y & 7;
    const int d0 = blockIdx.x * 64;

    __shared__ float Es[32][64];
    __shared__ float Fs[32][64];
    __shared__ float Xs[32][64];

    const int tid = threadIdx.x;
    const int r0 = (tid >> 4) << 2;
    const int c0 = (tid & 15) << 2;

    float accE[4][4], accF[4][4];
#pragma unroll
    for (int i = 0; i < 4; i++)
#pragma unroll
        for (int j = 0; j < 4; j++) { accE[i][j] = 0.0f; accF[i][j] = 0.0f; }

    const int nbeg = sp * (NN / LRS);

    for (int nt = 0; nt < (NN / LRS); nt += 32) {
        const int n0 = nbeg + nt;
        for (int i = tid; i < 512; i += 256) {
            const int row  = i >> 4;
            const int col4 = (i & 15) << 2;
            *(float4*)&Es[row][col4] = *(const float4*)(E  + (size_t)(n0 + row) * RR + col4);
            *(float4*)&Fs[row][col4] = *(const float4*)(Fm + (size_t)(n0 + row) * RR + col4);
            *(float4*)&Xs[row][col4] = *(const float4*)(x + ((size_t)b * NN + n0 + row) * DD + d0 + col4);
        }
        __syncthreads();
#pragma unroll 8
        for (int nn = 0; nn < 32; nn++) {
            float ae[4], af[4], xv[4];
#pragma unroll
            for (int i = 0; i < 4; i++) { ae[i] = Es[nn][r0 + i]; af[i] = Fs[nn][r0 + i]; }
#pragma unroll
            for (int j = 0; j < 4; j++) xv[j] = Xs[nn][c0 + j];
#pragma unroll
            for (int i = 0; i < 4; i++)
#pragma unroll
                for (int j = 0; j < 4; j++) {
                    accE[i][j] = fmaf(ae[i], xv[j], accE[i][j]);
                    accF[i][j] = fmaf(af[i], xv[j], accF[i][j]);
                }
        }
        __syncthreads();
    }

    float* OE = part + ((size_t)(0 * LRS + sp) * BB + b) * RR * DD;
    float* OF = part + ((size_t)(1 * LRS + sp) * BB + b) * RR * DD;
#pragma unroll
    for (int i = 0; i < 4; i++) {
        float4 ve = {accE[i][0], accE[i][1], accE[i][2], accE[i][3]};
        float4 vf = {accF[i][0], accF[i][1], accF[i][2], accF[i][3]};
        *(float4*)(OE + (size_t)(r0 + i) * DD + d0 + c0) = ve;
        *(float4*)(OF + (size_t)(r0 + i) * DD + d0 + c0) = vf;
    }
}

// reduce partials and emit fp16 hi/lo splits for the small GEMMs
__global__ void lr_reduce_split(const float* __restrict__ part,
                                __half* __restrict__ xEh, __half* __restrict__ xEl,
                                __half* __restrict__ xFh, __half* __restrict__ xFl)
{
    const int ELEMS = BB * RR * DD;  // 262144
    int i = blockIdx.x * blockDim.x + threadIdx.x;
    if (i >= 2 * ELEMS) return;
    const int pair = (i >= ELEMS);
    const int j = i - pair * ELEMS;
    const float* p = part + (size_t)pair * LRS * ELEMS;
    float s = 0.0f;
#pragma unroll
    for (int sp = 0; sp < LRS; sp++) s += p[(size_t)sp * ELEMS + j];
    __half hb = __float2half(s);
    __half lb = __float2half(s - __half2float(hb));
    if (pair) { xFh[j] = hb; xFl[j] = lb; }
    else      { xEh[j] = hb; xEl[j] = lb; }
}

// ---------------------------------------------------------------------------
// Attention: scores = Q.Klow/8, softmax over R=64 (bounded: no max-sub),
// ctx written as single fp16
// ---------------------------------------------------------------------------
__global__ __launch_bounds__(256, 4)
void linformer_attn(const float* __restrict__ Q, const float* __restrict__ Klow,
                    const float* __restrict__ Vlow, __half* __restrict__ ctx)
{
    const int b  = blockIdx.z;
    const int h  = blockIdx.y;
    const int n0 = blockIdx.x * 64;

    __shared__ float Ks[64][65];
    __shared__ float Vs[64][64];

    const int tid = threadIdx.x;
    for (int i = tid; i < 1024; i += 256) {
        const int r  = i >> 4;
        const int c4 = (i & 15) << 2;
        float4 kv = *(const float4*)(Klow + ((size_t)(b * RR + r)) * DD + h * HDIM + c4);
        Ks[r][c4 + 0] = kv.x; Ks[r][c4 + 1] = kv.y;
        Ks[r][c4 + 2] = kv.z; Ks[r][c4 + 3] = kv.w;
        float4 vv = *(const float4*)(Vlow + ((size_t)(b * RR + r)) * DD + h * HDIM + c4);
        *(float4*)&Vs[r][c4] = vv;
    }
    __syncthreads();

    const int warp = tid >> 5;
    const int lane = tid & 31;

    for (int rr = 0; rr < 8; rr++) {
        const int n = n0 + warp * 8 + rr;
        const float* qp = Q + ((size_t)(b * NN + n)) * DD + h * HDIM;
        const float q0 = qp[lane];
        const float q1 = qp[lane + 32];

        float s0 = 0.0f, s1 = 0.0f;
#pragma unroll
        for (int hd = 0; hd < 64; hd++) {
            float qv = __shfl_sync(0xffffffffu, (hd < 32) ? q0 : q1, hd & 31);
            s0 = fmaf(qv, Ks[lane][hd],      s0);
            s1 = fmaf(qv, Ks[lane + 32][hd], s1);
        }
        float e0 = __expf(s0 * 0.125f);
        float e1 = __expf(s1 * 0.125f);
        float sum = e0 + e1;
#pragma unroll
        for (int off = 16; off > 0; off >>= 1)
            sum += __shfl_xor_sync(0xffffffffu, sum, off);
        const float inv = 1.0f / sum;
        const float a0 = e0 * inv;
        const float a1 = e1 * inv;

        float o0 = 0.0f, o1 = 0.0f;
#pragma unroll
        for (int r = 0; r < 64; r++) {
            float av = __shfl_sync(0xffffffffu, (r < 32) ? a0 : a1, r & 31);
            o0 = fmaf(av, Vs[r][lane],      o0);
            o1 = fmaf(av, Vs[r][lane + 32], o1);
        }
        const size_t base = ((size_t)(b * NN + n)) * DD + h * HDIM;
        ctx[base + lane]      = __float2half(o0);
        ctx[base + lane + 32] = __float2half(o1);
    }
}

// ---------------------------------------------------------------------------
extern "C" void kernel_launch(void* const* d_in, const int* in_sizes, int n_in,
                              void* d_out, int out_size)
{
    const float* x  = (const float*)d_in[0];
    const float* Wq = (const float*)d_in[1];
    const float* Wk = (const float*)d_in[2];
    const float* Wv = (const float*)d_in[3];
    const float* Wo = (const float*)d_in[4];
    const float* bo = (const float*)d_in[5];
    const float* E  = (const float*)d_in[6];
    const float* Fm = (const float*)d_in[7];
    float* out = (float*)d_out;

    __half *xh, *wh, *wl, *ch, *xEh, *xEl, *xFh, *xFl;
    float *q, *kl, *vl, *part;
    cudaGetSymbolAddress((void**)&xh, g_xh);
    cudaGetSymbolAddress((void**)&wh, g_Wh);
    cudaGetSymbolAddress((void**)&wl, g_Wl);
    cudaGetSymbolAddress((void**)&q,  g_Q);
    cudaGetSymbolAddress((void**)&ch, g_ch);
    cudaGetSymbolAddress((void**)&part, g_part);
    cudaGetSymbolAddress((void**)&xEh, g_xEh);
    cudaGetSymbolAddress((void**)&xEl, g_xEl);
    cudaGetSymbolAddress((void**)&xFh, g_xFh);
    cudaGetSymbolAddress((void**)&xFl, g_xFl);
    cudaGetSymbolAddress((void**)&kl, g_Klow);
    cudaGetSymbolAddress((void**)&vl, g_Vlow);

    cudaFuncSetAttribute(gemm2p,      cudaFuncAttributeMaxDynamicSharedMemorySize, SMEM_GEMM);
    cudaFuncSetAttribute(gemm_splitk, cudaFuncAttributeMaxDynamicSharedMemorySize, SMEM_SMALL);

    // persistent side-stream + events (created once; identical enqueue each call)
    static cudaStream_t s1 = nullptr;
    static cudaEvent_t eFork = nullptr, eW = nullptr, eJoin = nullptr;
    if (s1 == nullptr) {
        cudaStreamCreateWithFlags(&s1, cudaStreamNonBlocking);
        cudaEventCreateWithFlags(&eFork, cudaEventDisableTiming);
        cudaEventCreateWithFlags(&eW,    cudaEventDisableTiming);
        cudaEventCreateWithFlags(&eJoin, cudaEventDisableTiming);
    }

    // ---- fork: Klow/Vlow chain on s1 (reads only raw inputs until splitk) ----
    cudaEventRecord(eFork, 0);
    cudaStreamWaitEvent(s1, eFork, 0);

    zero2_f32<<<(2*BB*RR*DD/4 + 255)/256, 256, 0, s1>>>(kl, vl, BB*RR*DD/4);
    lowrank_x<<<dim3(DD/64, BB*LRS), 256, 0, s1>>>(x, E, Fm, part);
    lr_reduce_split<<<(2*BB*RR*DD + 255)/256, 256, 0, s1>>>(part, xEh, xEl, xFh, xFl);

    // ---- main: weight cvt; record eW so s1's splitk safely reads wh/wl ----
    cvt_w4<<<dim3((DD*DD/4 + 255)/256, 4), 256>>>(Wq, Wk, Wv, Wo, wh, wl);
    cudaEventRecord(eW, 0);
    cudaStreamWaitEvent(s1, eW, 0);

    gemm_splitk<<<dim3(DD/128, 2, 16), 256, SMEM_SMALL, s1>>>(
        xEh, xEl, xFh, xFl, wh, wl, kl, vl);
    cudaEventRecord(eJoin, s1);

    // ---- main: x cvt (single fp16) + Q projection (2-pass) ----
    cvt_h<<<(MTOT*DD/4 + 255)/256, 256>>>(x, xh, MTOT*DD/4);
    gemm2p<<<dim3(DD/128, MTOT/128), 256, SMEM_GEMM>>>(
        xh, wh + 0*(size_t)DD*DD, wl + 0*(size_t)DD*DD, q, nullptr);

    // ---- join: attention needs Q + Klow/Vlow ----
    cudaStreamWaitEvent(0, eJoin, 0);

    linformer_attn<<<dim3(NN/64, HH, BB), 256>>>(q, kl, vl, ch);

    // ---- out = ctx @ Wo^T + bo (2-pass) ----
    gemm2p<<<dim3(DD/128, MTOT/128), 256, SMEM_GEMM>>>(
        ch, wh + 3*(size_t)DD*DD, wl + 3*(size_t)DD*DD, out, bo);
}